// round 2
// baseline (speedup 1.0000x reference)
#include <cuda_runtime.h>
#include <cstdint>

#define N_NODES 50000
#define N_EDGES 800000
#define DIM 128
#define HEADS 8
#define TILE_M 128
#define KT_STRIDE 513                 // uint2 stride per k-tile (8 k values), avoids staging bank conflicts
#define CS_STRIDE 132                 // float stride for epilogue C staging
#define SMEM_WP_U2 (16 * KT_STRIDE)   // 8208 uint2 = 65664 B
#define SMEM_CS_BYTES (128 * CS_STRIDE * 4)  // 67584 B (union with Ap region)
#define SMEM_BYTES (SMEM_WP_U2 * 8 + SMEM_CS_BYTES)  // 133248 B
#define GRID_PERSIST 148

// Scratch (allocation-free rule: __device__ globals)
__device__ float g_Q[N_NODES * DIM];
__device__ float g_K[N_NODES * DIM];
__device__ float g_V[N_NODES * DIM];
__device__ float g_z[N_NODES * HEADS];

// ---------------------------------------------------------------------------
// helpers
// ---------------------------------------------------------------------------
__device__ __forceinline__ uint32_t f2tf32(float f) {
    uint32_t r;
    asm("cvt.rna.tf32.f32 %0, %1;" : "=r"(r) : "f"(f));
    return r;
}

__device__ __forceinline__ void mma8(float c[4], uint32_t a0, uint32_t a1,
                                     uint32_t a2, uint32_t a3,
                                     uint32_t b0, uint32_t b1) {
    asm("mma.sync.aligned.m16n8k8.row.col.f32.tf32.tf32.f32 "
        "{%0,%1,%2,%3}, {%4,%5,%6,%7}, {%8,%9}, {%0,%1,%2,%3};\n"
        : "+f"(c[0]), "+f"(c[1]), "+f"(c[2]), "+f"(c[3])
        : "r"(a0), "r"(a1), "r"(a2), "r"(a3), "r"(b0), "r"(b1));
}

__device__ __forceinline__ void red_add_v4(float* p, float4 v) {
    asm volatile("red.global.add.v4.f32 [%0], {%1,%2,%3,%4};"
                 :: "l"(p), "f"(v.x), "f"(v.y), "f"(v.z), "f"(v.w) : "memory");
}

__device__ __forceinline__ void red_add_f32(float* p, float v) {
    asm volatile("red.global.add.f32 [%0], %1;" :: "l"(p), "f"(v) : "memory");
}

// Stage W[128][128] (row-major, k x n) into packed tf32 layout:
// Wp[kt*KT_STRIDE + n*4 + p] = uint2{ W[kt*8+p][n], W[kt*8+p+4][n] }
// uint32 view within a k-tile: index = n*8 + p*2 + slot
__device__ __forceinline__ void stage_W(uint2* Wp, const float* __restrict__ W) {
    int tid = threadIdx.x;
#pragma unroll 1
    for (int it = 0; it < 16; ++it) {
        int idx = it * 256 + tid;     // 0..4095
        int k = idx & 127;            // lanes vary k -> tolerable STS conflicts (once per block)
        int c = idx >> 7;             // float4 index over n
        float4 v = *(const float4*)&W[k * DIM + c * 4];
        int kt = k >> 3, p = k & 3, slot = (k >> 2) & 1;
        uint32_t* w32 = (uint32_t*)(Wp + kt * KT_STRIDE);
        int n0 = c * 4;
        w32[(n0 + 0) * 8 + p * 2 + slot] = f2tf32(v.x);
        w32[(n0 + 1) * 8 + p * 2 + slot] = f2tf32(v.y);
        w32[(n0 + 2) * 8 + p * 2 + slot] = f2tf32(v.z);
        w32[(n0 + 3) * 8 + p * 2 + slot] = f2tf32(v.w);
    }
}

// Stage A tile (128 rows x 128 k, row-major) into packed tf32 layout:
// Ap[kt*KT_STRIDE + r*4 + p] = uint2{ A[r][kt*8+p], A[r][kt*8+p+4] }
__device__ __forceinline__ void stage_A(uint2* Ap, const float* __restrict__ A,
                                        int row0, int M) {
    int tid = threadIdx.x;
#pragma unroll 1
    for (int it = 0; it < 16; ++it) {
        int idx = it * 256 + tid;     // 0..4095
        int r = idx >> 5;             // row in tile
        int c = idx & 31;             // float4 index over k
        int grow = row0 + r;
        float4 v = make_float4(0.f, 0.f, 0.f, 0.f);
        if (grow < M) v = *(const float4*)&A[(size_t)grow * DIM + c * 4];
        int kt = c >> 1, slot = c & 1;
        uint32_t* b32 = (uint32_t*)(Ap + kt * KT_STRIDE + r * 4);
        b32[0 * 2 + slot] = f2tf32(v.x);
        b32[1 * 2 + slot] = f2tf32(v.y);
        b32[2 * 2 + slot] = f2tf32(v.z);
        b32[3 * 2 + slot] = f2tf32(v.w);
    }
}

// Warp mainloop: 32 rows x 64 cols per warp, K=128
__device__ __forceinline__ void mma_tile(const uint2* Ap, const uint2* Wp,
                                         int wm, int wn, int lane,
                                         float c[2][8][4]) {
#pragma unroll 4
    for (int kt = 0; kt < 16; ++kt) {
        const uint2* ak = Ap + kt * KT_STRIDE;
        const uint2* wk = Wp + kt * KT_STRIDE;
        uint2 a00 = ak[wm * 4 + lane];            // rows wm+g      -> (a0, a2)
        uint2 a01 = ak[(wm + 8) * 4 + lane];      // rows wm+8+g    -> (a1, a3)
        uint2 a10 = ak[(wm + 16) * 4 + lane];
        uint2 a11 = ak[(wm + 24) * 4 + lane];
#pragma unroll
        for (int nf = 0; nf < 8; ++nf) {
            uint2 b = wk[(wn + nf * 8) * 4 + lane];
            mma8(c[0][nf], a00.x, a01.x, a00.y, a01.y, b.x, b.y);
            mma8(c[1][nf], a10.x, a11.x, a10.y, a11.y, b.x, b.y);
        }
    }
}

// ---------------------------------------------------------------------------
// Node projection GEMM: out[M,128] = A[M,128] @ W[128,128] + bias
// ---------------------------------------------------------------------------
__global__ __launch_bounds__(256, 1)
void gemm_node(const float* __restrict__ A, const float* __restrict__ W,
               const float* __restrict__ bias, float* __restrict__ out, int M) {
    extern __shared__ uint2 smem[];
    uint2* Wp = smem;
    uint2* Ap = smem + SMEM_WP_U2;
    int tid = threadIdx.x, lane = tid & 31, warp = tid >> 5;
    int wm = (warp & 3) * 32, wn = (warp >> 2) * 64;
    int g = lane >> 2, t = lane & 3;

    stage_W(Wp, W);
    float2 bias2[8];
#pragma unroll
    for (int nf = 0; nf < 8; ++nf)
        bias2[nf] = *(const float2*)&bias[wn + nf * 8 + t * 2];
    __syncthreads();

    int nTiles = (M + TILE_M - 1) / TILE_M;
#pragma unroll 1
    for (int tile = blockIdx.x; tile < nTiles; tile += gridDim.x) {
        stage_A(Ap, A, tile * TILE_M, M);
        __syncthreads();
        float c[2][8][4];
#pragma unroll
        for (int i = 0; i < 2; ++i)
#pragma unroll
            for (int j = 0; j < 8; ++j)
#pragma unroll
                for (int k = 0; k < 4; ++k) c[i][j][k] = 0.f;
        mma_tile(Ap, Wp, wm, wn, lane, c);
        __syncthreads();  // all warps done reading Ap before next stage
        // epilogue: direct STG
#pragma unroll
        for (int mf = 0; mf < 2; ++mf) {
            int r0 = tile * TILE_M + wm + mf * 16 + g;
#pragma unroll
            for (int nf = 0; nf < 8; ++nf) {
                int col = wn + nf * 8 + t * 2;
                if (r0 < M)
                    *(float2*)&out[(size_t)r0 * DIM + col] =
                        make_float2(c[mf][nf][0] + bias2[nf].x,
                                    c[mf][nf][1] + bias2[nf].y);
                if (r0 + 8 < M)
                    *(float2*)&out[(size_t)(r0 + 8) * DIM + col] =
                        make_float2(c[mf][nf][2] + bias2[nf].x,
                                    c[mf][nf][3] + bias2[nf].y);
            }
        }
    }
}

// ---------------------------------------------------------------------------
// Fused edge kernel: proj = e @ We + be, then score/e_out/s/scatter
// ---------------------------------------------------------------------------
__global__ __launch_bounds__(256, 1)
void gemm_edge(const float* __restrict__ Ein, const float* __restrict__ W,
               const float* __restrict__ bias, const int* __restrict__ src,
               const int* __restrict__ dst, float* __restrict__ hacc,
               float* __restrict__ eout) {
    extern __shared__ uint2 smem[];
    uint2* Wp = smem;
    uint2* Ap = smem + SMEM_WP_U2;
    float* Cs = (float*)Ap;  // union: C staging reuses A region
    int tid = threadIdx.x, lane = tid & 31, warp = tid >> 5;
    int wm = (warp & 3) * 32, wn = (warp >> 2) * 64;
    int g = lane >> 2, t = lane & 3;

    stage_W(Wp, W);
    float4 be4 = *(const float4*)&bias[lane * 4];
    __syncthreads();

    const int nTiles = N_EDGES / TILE_M;  // 6250, exact
#pragma unroll 1
    for (int tile = blockIdx.x; tile < nTiles; tile += gridDim.x) {
        stage_A(Ap, Ein, tile * TILE_M, N_EDGES);
        __syncthreads();
        float c[2][8][4];
#pragma unroll
        for (int i = 0; i < 2; ++i)
#pragma unroll
            for (int j = 0; j < 8; ++j)
#pragma unroll
                for (int k = 0; k < 4; ++k) c[i][j][k] = 0.f;
        mma_tile(Ap, Wp, wm, wn, lane, c);
        __syncthreads();  // Ap reads done -> safe to overwrite with Cs
        // store C fragments into shared for edge-major epilogue
#pragma unroll
        for (int mf = 0; mf < 2; ++mf) {
            int rr = wm + mf * 16 + g;
#pragma unroll
            for (int nf = 0; nf < 8; ++nf) {
                int col = wn + nf * 8 + t * 2;
                *(float2*)&Cs[rr * CS_STRIDE + col] =
                    make_float2(c[mf][nf][0], c[mf][nf][1]);
                *(float2*)&Cs[(rr + 8) * CS_STRIDE + col] =
                    make_float2(c[mf][nf][2], c[mf][nf][3]);
            }
        }
        __syncthreads();

        // epilogue: each warp owns 16 edges of this tile
        int rbase = warp * 16;
        int ebase = tile * TILE_M + rbase;
#pragma unroll 1
        for (int i = 0; i < 16; ++i) {
            int eidx = ebase + i;
            int sn = src[eidx];
            int dn = dst[eidx];
            float4 pr = *(float4*)&Cs[(rbase + i) * CS_STRIDE + lane * 4];
            pr.x += be4.x; pr.y += be4.y; pr.z += be4.z; pr.w += be4.w;
            float4 q = *(const float4*)&g_Q[(size_t)dn * DIM + lane * 4];
            float4 kk = *(const float4*)&g_K[(size_t)sn * DIM + lane * 4];
            float4 vv = *(const float4*)&g_V[(size_t)sn * DIM + lane * 4];
            float4 sc;
            sc.x = q.x * kk.x * 0.25f * pr.x;
            sc.y = q.y * kk.y * 0.25f * pr.y;
            sc.z = q.z * kk.z * 0.25f * pr.z;
            sc.w = q.w * kk.w * 0.25f * pr.w;
            *(float4*)&eout[(size_t)eidx * DIM + lane * 4] = sc;
            float hs = sc.x + sc.y + sc.z + sc.w;
            hs += __shfl_xor_sync(0xffffffffu, hs, 1);
            hs += __shfl_xor_sync(0xffffffffu, hs, 2);
            float s = expf(fminf(fmaxf(hs, -5.f), 5.f));
            float4 add = make_float4(vv.x * s, vv.y * s, vv.z * s, vv.w * s);
            red_add_v4(&hacc[(size_t)dn * DIM + lane * 4], add);
            if ((lane & 3) == 0)
                red_add_f32(&g_z[dn * HEADS + (lane >> 2)], s);
        }
        __syncthreads();  // Cs reads done before next tile's stage_A
    }
}

// ---------------------------------------------------------------------------
// finalize: h_out = wV / (z + 1e-6)
// ---------------------------------------------------------------------------
__global__ void finalize_kernel(float* __restrict__ hacc) {
    int i = blockIdx.x * blockDim.x + threadIdx.x;
    if (i < N_NODES * DIM) {
        int node = i >> 7;
        int head = (i >> 4) & 7;
        hacc[i] = hacc[i] / (g_z[node * HEADS + head] + 1e-6f);
    }
}

// ---------------------------------------------------------------------------
// launch
// ---------------------------------------------------------------------------
extern "C" void kernel_launch(void* const* d_in, const int* in_sizes, int n_in,
                              void* d_out, int out_size) {
    const float* h  = (const float*)d_in[0];
    const float* e  = (const float*)d_in[1];
    const int*   src = (const int*)d_in[2];
    const int*   dst = (const int*)d_in[3];
    const float* Wq = (const float*)d_in[4];
    const float* bq = (const float*)d_in[5];
    const float* Wk = (const float*)d_in[6];
    const float* bk = (const float*)d_in[7];
    const float* Wv = (const float*)d_in[8];
    const float* bv = (const float*)d_in[9];
    const float* We = (const float*)d_in[10];
    const float* be = (const float*)d_in[11];

    float* out  = (float*)d_out;
    float* hacc = out;                               // [N,H,D] accumulator -> h_out
    float* eout = out + (size_t)N_NODES * DIM;       // [E,H,D] e_out

    float *qp, *kp, *vp, *zp;
    cudaGetSymbolAddress((void**)&qp, g_Q);
    cudaGetSymbolAddress((void**)&kp, g_K);
    cudaGetSymbolAddress((void**)&vp, g_V);
    cudaGetSymbolAddress((void**)&zp, g_z);

    cudaFuncSetAttribute(gemm_node, cudaFuncAttributeMaxDynamicSharedMemorySize, SMEM_BYTES);
    cudaFuncSetAttribute(gemm_edge, cudaFuncAttributeMaxDynamicSharedMemorySize, SMEM_BYTES);

    cudaMemsetAsync(hacc, 0, (size_t)N_NODES * DIM * sizeof(float));
    cudaMemsetAsync(zp, 0, (size_t)N_NODES * HEADS * sizeof(float));

    gemm_node<<<GRID_PERSIST, 256, SMEM_BYTES>>>(h, Wq, bq, qp, N_NODES);
    gemm_node<<<GRID_PERSIST, 256, SMEM_BYTES>>>(h, Wk, bk, kp, N_NODES);
    gemm_node<<<GRID_PERSIST, 256, SMEM_BYTES>>>(h, Wv, bv, vp, N_NODES);
    gemm_edge<<<GRID_PERSIST, 256, SMEM_BYTES>>>(e, We, be, src, dst, hacc, eout);
    finalize_kernel<<<(N_NODES * DIM + 255) / 256, 256>>>(hacc);
}

// round 4
// speedup vs baseline: 1.6557x; 1.6557x over previous
#include <cuda_runtime.h>
#include <cstdint>

#define N_NODES 50000
#define N_EDGES 800000
#define DIM 128
#define HEADS 8
#define TILE_M 64
#define KTW 517                       // uint2 stride per k-tile for W (128 cols * 4 + 5 pad)
#define KTA 265                       // uint2 stride per k-tile for A (64 rows * 4 + 9 pad)
#define CS_STRIDE 132                 // float stride for epilogue C staging (528B, 16B-aligned rows)
#define SMEM_W_U2 (16 * KTW)          // 8272 uint2 = 66176 B
#define SMEM_A_U2 (16 * KTA)          // 4240 uint2 = 33920 B (Cs: 64*132*4=33792 B aliases, fits)
#define SMEM_BYTES ((SMEM_W_U2 + SMEM_A_U2) * 8)  // 100096 B -> 2 CTAs/SM
#define GRID 296                      // 2 per SM * 148

// Scratch (allocation-free rule: __device__ globals)
__device__ float g_Q[N_NODES * DIM];
__device__ float g_K[N_NODES * DIM];
__device__ float g_V[N_NODES * DIM];
__device__ float g_z[N_NODES * HEADS];

// ---------------------------------------------------------------------------
// helpers
// ---------------------------------------------------------------------------
__device__ __forceinline__ uint32_t f2tf32(float f) {
    uint32_t r;
    asm("cvt.rna.tf32.f32 %0, %1;" : "=r"(r) : "f"(f));
    return r;
}

__device__ __forceinline__ void mma8(float c[4], uint32_t a0, uint32_t a1,
                                     uint32_t a2, uint32_t a3,
                                     uint32_t b0, uint32_t b1) {
    asm("mma.sync.aligned.m16n8k8.row.col.f32.tf32.tf32.f32 "
        "{%0,%1,%2,%3}, {%4,%5,%6,%7}, {%8,%9}, {%0,%1,%2,%3};\n"
        : "+f"(c[0]), "+f"(c[1]), "+f"(c[2]), "+f"(c[3])
        : "r"(a0), "r"(a1), "r"(a2), "r"(a3), "r"(b0), "r"(b1));
}

__device__ __forceinline__ void red_add_v4(float* p, float4 v) {
    asm volatile("red.global.add.v4.f32 [%0], {%1,%2,%3,%4};"
                 :: "l"(p), "f"(v.x), "f"(v.y), "f"(v.z), "f"(v.w) : "memory");
}

__device__ __forceinline__ void red_add_f32(float* p, float v) {
    asm volatile("red.global.add.f32 [%0], %1;" :: "l"(p), "f"(v) : "memory");
}

// Stage W[128][128] (row-major, k x n) into packed tf32 layout:
// within k-tile, uint32 index = n*8 + p*2 + slot, p=k&3, slot=(k>>2)&1
__device__ __forceinline__ void stage_W(uint2* Wp, const float* __restrict__ W) {
    int tid = threadIdx.x;
#pragma unroll 1
    for (int it = 0; it < 16; ++it) {
        int idx = it * 256 + tid;     // 0..4095
        int k = idx & 127;
        int c = idx >> 7;             // float4 index over n
        float4 v = *(const float4*)&W[k * DIM + c * 4];
        int kt = k >> 3, p = k & 3, slot = (k >> 2) & 1;
        uint32_t* w32 = (uint32_t*)(Wp + kt * KTW);
        int n0 = c * 4;
        w32[(n0 + 0) * 8 + p * 2 + slot] = f2tf32(v.x);
        w32[(n0 + 1) * 8 + p * 2 + slot] = f2tf32(v.y);
        w32[(n0 + 2) * 8 + p * 2 + slot] = f2tf32(v.z);
        w32[(n0 + 3) * 8 + p * 2 + slot] = f2tf32(v.w);
    }
}

// Stage A tile (64 rows x 128 k): Ap[kt*KTA + r*4 + p] = {A[r][kt*8+p], A[r][kt*8+p+4]}
__device__ __forceinline__ void stage_A(uint2* Ap, const float* __restrict__ A,
                                        int row0, int M) {
    int tid = threadIdx.x;
#pragma unroll 1
    for (int it = 0; it < 8; ++it) {
        int idx = it * 256 + tid;     // 0..2047
        int r = idx >> 5;             // row in tile (0..63)
        int c = idx & 31;             // float4 index over k
        int grow = row0 + r;
        float4 v = make_float4(0.f, 0.f, 0.f, 0.f);
        if (grow < M) v = *(const float4*)&A[(size_t)grow * DIM + c * 4];
        int kt = c >> 1, slot = c & 1;
        uint32_t* b32 = (uint32_t*)(Ap + kt * KTA + r * 4);
        b32[0 * 2 + slot] = f2tf32(v.x);
        b32[1 * 2 + slot] = f2tf32(v.y);
        b32[2 * 2 + slot] = f2tf32(v.z);
        b32[3 * 2 + slot] = f2tf32(v.w);
    }
}

// Warp mainloop: 32 rows x 32 cols per warp, K=128
__device__ __forceinline__ void mma_tile(const uint2* Ap, const uint2* Wp,
                                         int wm, int wn, int lane,
                                         float c[2][4][4]) {
#pragma unroll 4
    for (int kt = 0; kt < 16; ++kt) {
        const uint2* ak = Ap + kt * KTA;
        const uint2* wk = Wp + kt * KTW;
        uint2 a00 = ak[wm * 4 + lane];            // rows wm+g
        uint2 a01 = ak[(wm + 8) * 4 + lane];      // rows wm+8+g
        uint2 a10 = ak[(wm + 16) * 4 + lane];
        uint2 a11 = ak[(wm + 24) * 4 + lane];
#pragma unroll
        for (int nf = 0; nf < 4; ++nf) {
            uint2 b = wk[(wn + nf * 8) * 4 + lane];
            mma8(c[0][nf], a00.x, a01.x, a00.y, a01.y, b.x, b.y);
            mma8(c[1][nf], a10.x, a11.x, a10.y, a11.y, b.x, b.y);
        }
    }
}

// ---------------------------------------------------------------------------
// Fused node projections: out_w[M,128] = h @ W_w + b_w for w = blockIdx.y
// ---------------------------------------------------------------------------
__global__ __launch_bounds__(256, 2)
void gemm_node(const float* __restrict__ A,
               const float* __restrict__ W0, const float* __restrict__ W1,
               const float* __restrict__ W2, const float* __restrict__ B0,
               const float* __restrict__ B1, const float* __restrict__ B2,
               float* __restrict__ O0, float* __restrict__ O1,
               float* __restrict__ O2, int M) {
    extern __shared__ uint2 smem[];
    uint2* Wp = smem;
    uint2* Ap = smem + SMEM_W_U2;
    int which = blockIdx.y;
    const float* W = (which == 0) ? W0 : (which == 1) ? W1 : W2;
    const float* bias = (which == 0) ? B0 : (which == 1) ? B1 : B2;
    float* out = (which == 0) ? O0 : (which == 1) ? O1 : O2;

    int tid = threadIdx.x, lane = tid & 31, warp = tid >> 5;
    int wm = (warp & 1) * 32, wn = (warp >> 1) * 32;
    int g = lane >> 2, t = lane & 3;

    stage_W(Wp, W);
    float2 bias2[4];
#pragma unroll
    for (int nf = 0; nf < 4; ++nf)
        bias2[nf] = *(const float2*)&bias[wn + nf * 8 + t * 2];
    __syncthreads();

    int nTiles = (M + TILE_M - 1) / TILE_M;
#pragma unroll 1
    for (int tile = blockIdx.x; tile < nTiles; tile += gridDim.x) {
        stage_A(Ap, A, tile * TILE_M, M);
        __syncthreads();
        float c[2][4][4];
#pragma unroll
        for (int i = 0; i < 2; ++i)
#pragma unroll
            for (int j = 0; j < 4; ++j)
#pragma unroll
                for (int k = 0; k < 4; ++k) c[i][j][k] = 0.f;
        mma_tile(Ap, Wp, wm, wn, lane, c);
        __syncthreads();
#pragma unroll
        for (int mf = 0; mf < 2; ++mf) {
            int r0 = tile * TILE_M + wm + mf * 16 + g;
#pragma unroll
            for (int nf = 0; nf < 4; ++nf) {
                int col = wn + nf * 8 + t * 2;
                if (r0 < M)
                    *(float2*)&out[(size_t)r0 * DIM + col] =
                        make_float2(c[mf][nf][0] + bias2[nf].x,
                                    c[mf][nf][1] + bias2[nf].y);
                if (r0 + 8 < M)
                    *(float2*)&out[(size_t)(r0 + 8) * DIM + col] =
                        make_float2(c[mf][nf][2] + bias2[nf].x,
                                    c[mf][nf][3] + bias2[nf].y);
            }
        }
    }
}

// ---------------------------------------------------------------------------
// Fused edge kernel: proj = e @ We + be, then score/e_out/s/scatter
// ---------------------------------------------------------------------------
__global__ __launch_bounds__(256, 2)
void gemm_edge(const float* __restrict__ Ein, const float* __restrict__ W,
               const float* __restrict__ bias, const int* __restrict__ src,
               const int* __restrict__ dst, float* __restrict__ hacc,
               float* __restrict__ eout) {
    extern __shared__ uint2 smem[];
    uint2* Wp = smem;
    uint2* Ap = smem + SMEM_W_U2;
    float* Cs = (float*)Ap;  // union: C staging reuses A region
    int tid = threadIdx.x, lane = tid & 31, warp = tid >> 5;
    int wm = (warp & 1) * 32, wn = (warp >> 1) * 32;
    int g = lane >> 2, t = lane & 3;

    stage_W(Wp, W);
    float4 be4 = *(const float4*)&bias[lane * 4];
    __syncthreads();

    const int nTiles = N_EDGES / TILE_M;  // 12500 exact
#pragma unroll 1
    for (int tile = blockIdx.x; tile < nTiles; tile += gridDim.x) {
        stage_A(Ap, Ein, tile * TILE_M, N_EDGES);
        __syncthreads();
        float c[2][4][4];
#pragma unroll
        for (int i = 0; i < 2; ++i)
#pragma unroll
            for (int j = 0; j < 4; ++j)
#pragma unroll
                for (int k = 0; k < 4; ++k) c[i][j][k] = 0.f;
        mma_tile(Ap, Wp, wm, wn, lane, c);
        __syncthreads();  // Ap reads done -> safe to overwrite with Cs
#pragma unroll
        for (int mf = 0; mf < 2; ++mf) {
            int rr = wm + mf * 16 + g;
#pragma unroll
            for (int nf = 0; nf < 4; ++nf) {
                int col = wn + nf * 8 + t * 2;
                *(float2*)&Cs[rr * CS_STRIDE + col] =
                    make_float2(c[mf][nf][0], c[mf][nf][1]);
                *(float2*)&Cs[(rr + 8) * CS_STRIDE + col] =
                    make_float2(c[mf][nf][2], c[mf][nf][3]);
            }
        }
        __syncthreads();

        // epilogue: each warp owns 8 edges of this tile
        int rbase = warp * 8;
        int ebase = tile * TILE_M + rbase;
        int sn[8], dn[8];
#pragma unroll
        for (int i = 0; i < 8; ++i) {
            sn[i] = src[ebase + i];
            dn[i] = dst[ebase + i];
        }
#pragma unroll 2
        for (int i = 0; i < 8; ++i) {
            float4 q = *(const float4*)&g_Q[(size_t)dn[i] * DIM + lane * 4];
            float4 kk = *(const float4*)&g_K[(size_t)sn[i] * DIM + lane * 4];
            float4 vv = *(const float4*)&g_V[(size_t)sn[i] * DIM + lane * 4];
            float4 pr = *(float4*)&Cs[(rbase + i) * CS_STRIDE + lane * 4];
            pr.x += be4.x; pr.y += be4.y; pr.z += be4.z; pr.w += be4.w;
            float4 sc;
            sc.x = q.x * kk.x * 0.25f * pr.x;
            sc.y = q.y * kk.y * 0.25f * pr.y;
            sc.z = q.z * kk.z * 0.25f * pr.z;
            sc.w = q.w * kk.w * 0.25f * pr.w;
            *(float4*)&eout[(size_t)(ebase + i) * DIM + lane * 4] = sc;
            float hs = sc.x + sc.y + sc.z + sc.w;
            hs += __shfl_xor_sync(0xffffffffu, hs, 1);
            hs += __shfl_xor_sync(0xffffffffu, hs, 2);
            float s = expf(fminf(fmaxf(hs, -5.f), 5.f));
            float4 add = make_float4(vv.x * s, vv.y * s, vv.z * s, vv.w * s);
            red_add_v4(&hacc[(size_t)dn[i] * DIM + lane * 4], add);
            if ((lane & 3) == 0)
                red_add_f32(&g_z[dn[i] * HEADS + (lane >> 2)], s);
        }
        __syncthreads();  // Cs reads done before next tile's stage_A
    }
}

// ---------------------------------------------------------------------------
// finalize: h_out = wV / (z + 1e-6)
// ---------------------------------------------------------------------------
__global__ void finalize_kernel(float* __restrict__ hacc) {
    int i = blockIdx.x * blockDim.x + threadIdx.x;
    if (i < N_NODES * DIM) {
        int node = i >> 7;
        int head = (i >> 4) & 7;
        hacc[i] = hacc[i] / (g_z[node * HEADS + head] + 1e-6f);
    }
}

// ---------------------------------------------------------------------------
// launch
// ---------------------------------------------------------------------------
extern "C" void kernel_launch(void* const* d_in, const int* in_sizes, int n_in,
                              void* d_out, int out_size) {
    const float* h  = (const float*)d_in[0];
    const float* e  = (const float*)d_in[1];
    const int*   src = (const int*)d_in[2];
    const int*   dst = (const int*)d_in[3];
    const float* Wq = (const float*)d_in[4];
    const float* bq = (const float*)d_in[5];
    const float* Wk = (const float*)d_in[6];
    const float* bk = (const float*)d_in[7];
    const float* Wv = (const float*)d_in[8];
    const float* bv = (const float*)d_in[9];
    const float* We = (const float*)d_in[10];
    const float* be = (const float*)d_in[11];

    float* out  = (float*)d_out;
    float* hacc = out;                               // [N,H,D] accumulator -> h_out
    float* eout = out + (size_t)N_NODES * DIM;       // [E,H,D] e_out

    float *qp, *kp, *vp, *zp;
    cudaGetSymbolAddress((void**)&qp, g_Q);
    cudaGetSymbolAddress((void**)&kp, g_K);
    cudaGetSymbolAddress((void**)&vp, g_V);
    cudaGetSymbolAddress((void**)&zp, g_z);

    cudaFuncSetAttribute(gemm_node, cudaFuncAttributeMaxDynamicSharedMemorySize, SMEM_BYTES);
    cudaFuncSetAttribute(gemm_edge, cudaFuncAttributeMaxDynamicSharedMemorySize, SMEM_BYTES);

    cudaMemsetAsync(hacc, 0, (size_t)N_NODES * DIM * sizeof(float));
    cudaMemsetAsync(zp, 0, (size_t)N_NODES * HEADS * sizeof(float));

    dim3 ngrid(GRID, 3);
    gemm_node<<<ngrid, 256, SMEM_BYTES>>>(h, Wq, Wk, Wv, bq, bk, bv,
                                          qp, kp, vp, N_NODES);
    gemm_edge<<<GRID, 256, SMEM_BYTES>>>(e, We, be, src, dst, hacc, eout);
    finalize_kernel<<<(N_NODES * DIM + 255) / 256, 256>>>(hacc);
}

// round 5
// speedup vs baseline: 2.0804x; 1.2565x over previous
#include <cuda_runtime.h>
#include <cstdint>

#define N_NODES 50000
#define N_EDGES 800000
#define DIM 128
#define HEADS 8
#define TILE_M 64
#define KTW 517                       // uint2 stride per k-tile for W (128 cols * 4 + 5 pad)
#define KTA 265                       // uint2 stride per k-tile for A (64 rows * 4 + 9 pad)
#define CS_STRIDE 132                 // float stride for epilogue C staging (528B, 16B-aligned rows)
#define SMEM_W_U2 (16 * KTW)          // 8272 uint2 = 66176 B
#define SMEM_A_U2 (16 * KTA)          // 4240 uint2 = 33920 B (Cs: 64*132*4=33792 B aliases, fits)
#define SMEM_BYTES ((SMEM_W_U2 + SMEM_A_U2) * 8)  // 100096 B -> 2 CTAs/SM
#define GRID 296                      // 2 per SM * 148

// Scratch (allocation-free rule: __device__ globals)
__device__ float g_Q[N_NODES * DIM];
__device__ float g_K[N_NODES * DIM];
__device__ float g_V[N_NODES * DIM];
__device__ float g_z[N_NODES * HEADS];

// ---------------------------------------------------------------------------
// helpers
// ---------------------------------------------------------------------------
__device__ __forceinline__ uint32_t f2tf32(float f) {
    uint32_t r;
    asm("cvt.rna.tf32.f32 %0, %1;" : "=r"(r) : "f"(f));
    return r;
}

__device__ __forceinline__ void mma8(float c[4], uint32_t a0, uint32_t a1,
                                     uint32_t a2, uint32_t a3,
                                     uint32_t b0, uint32_t b1) {
    asm("mma.sync.aligned.m16n8k8.row.col.f32.tf32.tf32.f32 "
        "{%0,%1,%2,%3}, {%4,%5,%6,%7}, {%8,%9}, {%0,%1,%2,%3};\n"
        : "+f"(c[0]), "+f"(c[1]), "+f"(c[2]), "+f"(c[3])
        : "r"(a0), "r"(a1), "r"(a2), "r"(a3), "r"(b0), "r"(b1));
}

__device__ __forceinline__ void red_add_v4(float* p, float4 v) {
    asm volatile("red.global.add.v4.f32 [%0], {%1,%2,%3,%4};"
                 :: "l"(p), "f"(v.x), "f"(v.y), "f"(v.z), "f"(v.w) : "memory");
}

__device__ __forceinline__ void red_add_f32(float* p, float v) {
    asm volatile("red.global.add.f32 [%0], %1;" :: "l"(p), "f"(v) : "memory");
}

// Stage W[128][128] (row-major, k x n) into packed tf32 layout:
// within k-tile, uint32 index = n*8 + p*2 + slot, p=k&3, slot=(k>>2)&1
__device__ __forceinline__ void stage_W(uint2* Wp, const float* __restrict__ W) {
    int tid = threadIdx.x;
#pragma unroll 1
    for (int it = 0; it < 16; ++it) {
        int idx = it * 256 + tid;     // 0..4095
        int k = idx & 127;
        int c = idx >> 7;             // float4 index over n
        float4 v = *(const float4*)&W[k * DIM + c * 4];
        int kt = k >> 3, p = k & 3, slot = (k >> 2) & 1;
        uint32_t* w32 = (uint32_t*)(Wp + kt * KTW);
        int n0 = c * 4;
        w32[(n0 + 0) * 8 + p * 2 + slot] = f2tf32(v.x);
        w32[(n0 + 1) * 8 + p * 2 + slot] = f2tf32(v.y);
        w32[(n0 + 2) * 8 + p * 2 + slot] = f2tf32(v.z);
        w32[(n0 + 3) * 8 + p * 2 + slot] = f2tf32(v.w);
    }
}

// Prefetch A tile into registers (8 float4 per thread). stream=evict-first.
template <bool STREAM>
__device__ __forceinline__ void prefetch_A(float4 v[8], const float* __restrict__ A,
                                           int row0, int M, int tid) {
#pragma unroll
    for (int it = 0; it < 8; ++it) {
        int idx = it * 256 + tid;     // 0..2047
        int r = idx >> 5;             // row in tile (0..63)
        int c = idx & 31;             // float4 index over k
        int grow = row0 + r;
        if (grow < M) {
            const float4* p = (const float4*)&A[(size_t)grow * DIM + c * 4];
            v[it] = STREAM ? __ldcs(p) : __ldg(p);
        } else {
            v[it] = make_float4(0.f, 0.f, 0.f, 0.f);
        }
    }
}

// Store prefetched regs into packed tf32 A layout.
__device__ __forceinline__ void store_A(uint2* Ap, const float4 v[8], int tid) {
#pragma unroll
    for (int it = 0; it < 8; ++it) {
        int idx = it * 256 + tid;
        int r = idx >> 5;
        int c = idx & 31;
        int kt = c >> 1, slot = c & 1;
        uint32_t* b32 = (uint32_t*)(Ap + kt * KTA + r * 4);
        b32[0 * 2 + slot] = f2tf32(v[it].x);
        b32[1 * 2 + slot] = f2tf32(v[it].y);
        b32[2 * 2 + slot] = f2tf32(v[it].z);
        b32[3 * 2 + slot] = f2tf32(v[it].w);
    }
}

// Warp mainloop: 32 rows x 32 cols per warp, K=128
__device__ __forceinline__ void mma_tile(const uint2* Ap, const uint2* Wp,
                                         int wm, int wn, int lane,
                                         float c[2][4][4]) {
#pragma unroll 4
    for (int kt = 0; kt < 16; ++kt) {
        const uint2* ak = Ap + kt * KTA;
        const uint2* wk = Wp + kt * KTW;
        uint2 a00 = ak[wm * 4 + lane];            // rows wm+g
        uint2 a01 = ak[(wm + 8) * 4 + lane];      // rows wm+8+g
        uint2 a10 = ak[(wm + 16) * 4 + lane];
        uint2 a11 = ak[(wm + 24) * 4 + lane];
#pragma unroll
        for (int nf = 0; nf < 4; ++nf) {
            uint2 b = wk[(wn + nf * 8) * 4 + lane];
            mma8(c[0][nf], a00.x, a01.x, a00.y, a01.y, b.x, b.y);
            mma8(c[1][nf], a10.x, a11.x, a10.y, a11.y, b.x, b.y);
        }
    }
}

// ---------------------------------------------------------------------------
// Fused node projections: out_w[M,128] = h @ W_w + b_w for w = blockIdx.y
// ---------------------------------------------------------------------------
__global__ __launch_bounds__(256, 2)
void gemm_node(const float* __restrict__ A,
               const float* __restrict__ W0, const float* __restrict__ W1,
               const float* __restrict__ W2, const float* __restrict__ B0,
               const float* __restrict__ B1, const float* __restrict__ B2,
               float* __restrict__ O0, float* __restrict__ O1,
               float* __restrict__ O2, int M) {
    extern __shared__ uint2 smem[];
    uint2* Wp = smem;
    uint2* Ap = smem + SMEM_W_U2;
    int which = blockIdx.y;
    const float* W = (which == 0) ? W0 : (which == 1) ? W1 : W2;
    const float* bias = (which == 0) ? B0 : (which == 1) ? B1 : B2;
    float* out = (which == 0) ? O0 : (which == 1) ? O1 : O2;

    int tid = threadIdx.x, lane = tid & 31, warp = tid >> 5;
    int wm = (warp & 1) * 32, wn = (warp >> 1) * 32;
    int g = lane >> 2, t = lane & 3;

    stage_W(Wp, W);
    float2 bias2[4];
#pragma unroll
    for (int nf = 0; nf < 4; ++nf)
        bias2[nf] = *(const float2*)&bias[wn + nf * 8 + t * 2];

    int nTiles = (M + TILE_M - 1) / TILE_M;
    int tile = blockIdx.x;
    float4 cur[8];
    if (tile < nTiles) prefetch_A<false>(cur, A, tile * TILE_M, M, tid);
    __syncthreads();

#pragma unroll 1
    for (; tile < nTiles; tile += gridDim.x) {
        store_A(Ap, cur, tid);
        __syncthreads();
        int nxt = tile + gridDim.x;
        if (nxt < nTiles) prefetch_A<false>(cur, A, nxt * TILE_M, M, tid);
        float c[2][4][4];
#pragma unroll
        for (int i = 0; i < 2; ++i)
#pragma unroll
            for (int j = 0; j < 4; ++j)
#pragma unroll
                for (int k = 0; k < 4; ++k) c[i][j][k] = 0.f;
        mma_tile(Ap, Wp, wm, wn, lane, c);
        __syncthreads();
#pragma unroll
        for (int mf = 0; mf < 2; ++mf) {
            int r0 = tile * TILE_M + wm + mf * 16 + g;
#pragma unroll
            for (int nf = 0; nf < 4; ++nf) {
                int col = wn + nf * 8 + t * 2;
                if (r0 < M)
                    *(float2*)&out[(size_t)r0 * DIM + col] =
                        make_float2(c[mf][nf][0] + bias2[nf].x,
                                    c[mf][nf][1] + bias2[nf].y);
                if (r0 + 8 < M)
                    *(float2*)&out[(size_t)(r0 + 8) * DIM + col] =
                        make_float2(c[mf][nf][2] + bias2[nf].x,
                                    c[mf][nf][3] + bias2[nf].y);
            }
        }
    }
}

// ---------------------------------------------------------------------------
// Fused edge kernel: proj = e @ We + be, then score/e_out/s/scatter
// ---------------------------------------------------------------------------
__global__ __launch_bounds__(256, 2)
void gemm_edge(const float* __restrict__ Ein, const float* __restrict__ W,
               const float* __restrict__ bias, const int* __restrict__ src,
               const int* __restrict__ dst, float* __restrict__ hacc,
               float* __restrict__ eout) {
    extern __shared__ uint2 smem[];
    uint2* Wp = smem;
    uint2* Ap = smem + SMEM_W_U2;
    float* Cs = (float*)Ap;  // union: C staging reuses A region
    int tid = threadIdx.x, lane = tid & 31, warp = tid >> 5;
    int wm = (warp & 1) * 32, wn = (warp >> 1) * 32;
    int g = lane >> 2, t = lane & 3;

    stage_W(Wp, W);
    float4 be4 = *(const float4*)&bias[lane * 4];

    const int nTiles = N_EDGES / TILE_M;  // 12500 exact
    int tile = blockIdx.x;
    float4 cur[8];
    if (tile < nTiles) prefetch_A<true>(cur, Ein, tile * TILE_M, N_EDGES, tid);
    __syncthreads();

#pragma unroll 1
    for (; tile < nTiles; tile += gridDim.x) {
        store_A(Ap, cur, tid);
        __syncthreads();
        float c[2][4][4];
#pragma unroll
        for (int i = 0; i < 2; ++i)
#pragma unroll
            for (int j = 0; j < 4; ++j)
#pragma unroll
                for (int k = 0; k < 4; ++k) c[i][j][k] = 0.f;
        mma_tile(Ap, Wp, wm, wn, lane, c);
        // prefetch next tile: overlaps Cs-write + gather/scatter epilogue
        int nxt = tile + gridDim.x;
        if (nxt < nTiles) prefetch_A<true>(cur, Ein, nxt * TILE_M, N_EDGES, tid);
        __syncthreads();  // Ap reads done -> safe to overwrite with Cs
#pragma unroll
        for (int mf = 0; mf < 2; ++mf) {
            int rr = wm + mf * 16 + g;
#pragma unroll
            for (int nf = 0; nf < 4; ++nf) {
                int col = wn + nf * 8 + t * 2;
                *(float2*)&Cs[rr * CS_STRIDE + col] =
                    make_float2(c[mf][nf][0], c[mf][nf][1]);
                *(float2*)&Cs[(rr + 8) * CS_STRIDE + col] =
                    make_float2(c[mf][nf][2], c[mf][nf][3]);
            }
        }
        __syncthreads();

        // epilogue: each warp owns 8 edges of this tile
        int rbase = warp * 8;
        int ebase = tile * TILE_M + rbase;
        int sn[8], dn[8];
#pragma unroll
        for (int i = 0; i < 8; ++i) {
            sn[i] = __ldg(&src[ebase + i]);
            dn[i] = __ldg(&dst[ebase + i]);
        }
#pragma unroll 2
        for (int i = 0; i < 8; ++i) {
            float4 q = *(const float4*)&g_Q[(size_t)dn[i] * DIM + lane * 4];
            float4 kk = *(const float4*)&g_K[(size_t)sn[i] * DIM + lane * 4];
            float4 vv = *(const float4*)&g_V[(size_t)sn[i] * DIM + lane * 4];
            float4 pr = *(float4*)&Cs[(rbase + i) * CS_STRIDE + lane * 4];
            pr.x += be4.x; pr.y += be4.y; pr.z += be4.z; pr.w += be4.w;
            float4 sc;
            sc.x = q.x * kk.x * 0.25f * pr.x;
            sc.y = q.y * kk.y * 0.25f * pr.y;
            sc.z = q.z * kk.z * 0.25f * pr.z;
            sc.w = q.w * kk.w * 0.25f * pr.w;
            __stcs((float4*)&eout[(size_t)(ebase + i) * DIM + lane * 4], sc);
            float hs = sc.x + sc.y + sc.z + sc.w;
            hs += __shfl_xor_sync(0xffffffffu, hs, 1);
            hs += __shfl_xor_sync(0xffffffffu, hs, 2);
            float s = expf(fminf(fmaxf(hs, -5.f), 5.f));
            float4 add = make_float4(vv.x * s, vv.y * s, vv.z * s, vv.w * s);
            red_add_v4(&hacc[(size_t)dn[i] * DIM + lane * 4], add);
            if ((lane & 3) == 0)
                red_add_f32(&g_z[dn[i] * HEADS + (lane >> 2)], s);
        }
        __syncthreads();  // Cs reads done before next tile's stage_A
    }
}

// ---------------------------------------------------------------------------
// finalize: h_out = wV / (z + 1e-6)
// ---------------------------------------------------------------------------
__global__ void finalize_kernel(float* __restrict__ hacc) {
    int i = blockIdx.x * blockDim.x + threadIdx.x;
    if (i < N_NODES * DIM) {
        int node = i >> 7;
        int head = (i >> 4) & 7;
        hacc[i] = hacc[i] / (g_z[node * HEADS + head] + 1e-6f);
    }
}

// ---------------------------------------------------------------------------
// launch
// ---------------------------------------------------------------------------
extern "C" void kernel_launch(void* const* d_in, const int* in_sizes, int n_in,
                              void* d_out, int out_size) {
    const float* h  = (const float*)d_in[0];
    const float* e  = (const float*)d_in[1];
    const int*   src = (const int*)d_in[2];
    const int*   dst = (const int*)d_in[3];
    const float* Wq = (const float*)d_in[4];
    const float* bq = (const float*)d_in[5];
    const float* Wk = (const float*)d_in[6];
    const float* bk = (const float*)d_in[7];
    const float* Wv = (const float*)d_in[8];
    const float* bv = (const float*)d_in[9];
    const float* We = (const float*)d_in[10];
    const float* be = (const float*)d_in[11];

    float* out  = (float*)d_out;
    float* hacc = out;                               // [N,H,D] accumulator -> h_out
    float* eout = out + (size_t)N_NODES * DIM;       // [E,H,D] e_out

    float *qp, *kp, *vp, *zp;
    cudaGetSymbolAddress((void**)&qp, g_Q);
    cudaGetSymbolAddress((void**)&kp, g_K);
    cudaGetSymbolAddress((void**)&vp, g_V);
    cudaGetSymbolAddress((void**)&zp, g_z);

    cudaFuncSetAttribute(gemm_node, cudaFuncAttributeMaxDynamicSharedMemorySize, SMEM_BYTES);
    cudaFuncSetAttribute(gemm_edge, cudaFuncAttributeMaxDynamicSharedMemorySize, SMEM_BYTES);

    cudaMemsetAsync(hacc, 0, (size_t)N_NODES * DIM * sizeof(float));
    cudaMemsetAsync(zp, 0, (size_t)N_NODES * HEADS * sizeof(float));

    dim3 ngrid(GRID, 3);
    gemm_node<<<ngrid, 256, SMEM_BYTES>>>(h, Wq, Wk, Wv, bq, bk, bv,
                                          qp, kp, vp, N_NODES);
    gemm_edge<<<GRID, 256, SMEM_BYTES>>>(e, We, be, src, dst, hacc, eout);
    finalize_kernel<<<(N_NODES * DIM + 255) / 256, 256>>>(hacc);
}

// round 6
// speedup vs baseline: 2.2503x; 1.0816x over previous
#include <cuda_runtime.h>
#include <cstdint>

#define N_NODES 50000
#define N_EDGES 800000
#define DIM 128
#define HEADS 8
#define TILE_M 64
#define THREADS 512
#define KTW 517                       // uint2 stride per k-tile for W (128 cols * 4 + 5 pad)
#define KTA 265                       // uint2 stride per k-tile for A (64 rows * 4 + 9 pad)
#define CS_STRIDE 132                 // float stride for epilogue C staging (528B, 16B-aligned rows)
#define SMEM_W_U2 (16 * KTW)          // 8272 uint2 = 66176 B
#define SMEM_A_U2 (16 * KTA)          // 4240 uint2 = 33920 B (Cs: 64*132*4=33792 B aliases, fits)
#define SMEM_BYTES ((SMEM_W_U2 + SMEM_A_U2) * 8)  // 100096 B -> 2 CTAs/SM
#define GRID 296                      // 2 per SM * 148

// Scratch (allocation-free rule: __device__ globals)
__device__ float g_Q[N_NODES * DIM];
__device__ float g_K[N_NODES * DIM];
__device__ float g_V[N_NODES * DIM];
__device__ float g_z[N_NODES * HEADS];

// ---------------------------------------------------------------------------
// helpers
// ---------------------------------------------------------------------------
__device__ __forceinline__ uint32_t f2tf32(float f) {
    uint32_t r;
    asm("cvt.rna.tf32.f32 %0, %1;" : "=r"(r) : "f"(f));
    return r;
}

__device__ __forceinline__ void mma8(float c[4], uint32_t a0, uint32_t a1,
                                     uint32_t a2, uint32_t a3,
                                     uint32_t b0, uint32_t b1) {
    asm("mma.sync.aligned.m16n8k8.row.col.f32.tf32.tf32.f32 "
        "{%0,%1,%2,%3}, {%4,%5,%6,%7}, {%8,%9}, {%0,%1,%2,%3};\n"
        : "+f"(c[0]), "+f"(c[1]), "+f"(c[2]), "+f"(c[3])
        : "r"(a0), "r"(a1), "r"(a2), "r"(a3), "r"(b0), "r"(b1));
}

__device__ __forceinline__ void red_add_v4(float* p, float4 v) {
    asm volatile("red.global.add.v4.f32 [%0], {%1,%2,%3,%4};"
                 :: "l"(p), "f"(v.x), "f"(v.y), "f"(v.z), "f"(v.w) : "memory");
}

__device__ __forceinline__ void red_add_f32(float* p, float v) {
    asm volatile("red.global.add.f32 [%0], %1;" :: "l"(p), "f"(v) : "memory");
}

// Stage W[128][128] (row-major, k x n) into packed tf32 layout:
// within k-tile, uint32 index = n*8 + p*2 + slot, p=k&3, slot=(k>>2)&1
__device__ __forceinline__ void stage_W(uint2* Wp, const float* __restrict__ W) {
    int tid = threadIdx.x;
#pragma unroll 1
    for (int it = 0; it < 8; ++it) {
        int idx = it * THREADS + tid; // 0..4095
        int k = idx & 127;
        int c = idx >> 7;             // float4 index over n
        float4 v = *(const float4*)&W[k * DIM + c * 4];
        int kt = k >> 3, p = k & 3, slot = (k >> 2) & 1;
        uint32_t* w32 = (uint32_t*)(Wp + kt * KTW);
        int n0 = c * 4;
        w32[(n0 + 0) * 8 + p * 2 + slot] = f2tf32(v.x);
        w32[(n0 + 1) * 8 + p * 2 + slot] = f2tf32(v.y);
        w32[(n0 + 2) * 8 + p * 2 + slot] = f2tf32(v.z);
        w32[(n0 + 3) * 8 + p * 2 + slot] = f2tf32(v.w);
    }
}

// Prefetch A tile into registers (4 float4 per thread). stream=evict-first.
template <bool STREAM>
__device__ __forceinline__ void prefetch_A(float4 v[4], const float* __restrict__ A,
                                           int row0, int M, int tid) {
#pragma unroll
    for (int it = 0; it < 4; ++it) {
        int idx = it * THREADS + tid; // 0..2047
        int r = idx >> 5;             // row in tile (0..63)
        int c = idx & 31;             // float4 index over k
        int grow = row0 + r;
        if (grow < M) {
            const float4* p = (const float4*)&A[(size_t)grow * DIM + c * 4];
            v[it] = STREAM ? __ldcs(p) : __ldg(p);
        } else {
            v[it] = make_float4(0.f, 0.f, 0.f, 0.f);
        }
    }
}

// Store prefetched regs into packed tf32 A layout.
__device__ __forceinline__ void store_A(uint2* Ap, const float4 v[4], int tid) {
#pragma unroll
    for (int it = 0; it < 4; ++it) {
        int idx = it * THREADS + tid;
        int r = idx >> 5;
        int c = idx & 31;
        int kt = c >> 1, slot = c & 1;
        uint32_t* b32 = (uint32_t*)(Ap + kt * KTA + r * 4);
        b32[0 * 2 + slot] = f2tf32(v[it].x);
        b32[1 * 2 + slot] = f2tf32(v[it].y);
        b32[2 * 2 + slot] = f2tf32(v[it].z);
        b32[3 * 2 + slot] = f2tf32(v[it].w);
    }
}

// Warp mainloop: 16 rows x 32 cols per warp, K=128
__device__ __forceinline__ void mma_tile(const uint2* Ap, const uint2* Wp,
                                         int wm, int wn, int lane,
                                         float c[4][4]) {
#pragma unroll 4
    for (int kt = 0; kt < 16; ++kt) {
        const uint2* ak = Ap + kt * KTA;
        const uint2* wk = Wp + kt * KTW;
        uint2 a0 = ak[wm * 4 + lane];             // rows wm+g      -> (a0, a2)
        uint2 a1 = ak[(wm + 8) * 4 + lane];       // rows wm+8+g    -> (a1, a3)
#pragma unroll
        for (int nf = 0; nf < 4; ++nf) {
            uint2 b = wk[(wn + nf * 8) * 4 + lane];
            mma8(c[nf], a0.x, a1.x, a0.y, a1.y, b.x, b.y);
        }
    }
}

// ---------------------------------------------------------------------------
// Fused node projections: out_w[M,128] = h @ W_w + b_w for w = blockIdx.y
// ---------------------------------------------------------------------------
__global__ __launch_bounds__(THREADS, 2)
void gemm_node(const float* __restrict__ A,
               const float* __restrict__ W0, const float* __restrict__ W1,
               const float* __restrict__ W2, const float* __restrict__ B0,
               const float* __restrict__ B1, const float* __restrict__ B2,
               float* __restrict__ O0, float* __restrict__ O1,
               float* __restrict__ O2, int M) {
    extern __shared__ uint2 smem[];
    uint2* Wp = smem;
    uint2* Ap = smem + SMEM_W_U2;
    int which = blockIdx.y;
    const float* W = (which == 0) ? W0 : (which == 1) ? W1 : W2;
    const float* bias = (which == 0) ? B0 : (which == 1) ? B1 : B2;
    float* out = (which == 0) ? O0 : (which == 1) ? O1 : O2;

    int tid = threadIdx.x, lane = tid & 31, warp = tid >> 5;
    int wm = (warp & 3) * 16, wn = (warp >> 2) * 32;
    int g = lane >> 2, t = lane & 3;

    stage_W(Wp, W);
    float2 bias2[4];
#pragma unroll
    for (int nf = 0; nf < 4; ++nf)
        bias2[nf] = *(const float2*)&bias[wn + nf * 8 + t * 2];

    int nTiles = (M + TILE_M - 1) / TILE_M;
    int tile = blockIdx.x;
    float4 cur[4];
    if (tile < nTiles) prefetch_A<false>(cur, A, tile * TILE_M, M, tid);
    __syncthreads();

#pragma unroll 1
    for (; tile < nTiles; tile += gridDim.x) {
        store_A(Ap, cur, tid);
        __syncthreads();
        int nxt = tile + gridDim.x;
        if (nxt < nTiles) prefetch_A<false>(cur, A, nxt * TILE_M, M, tid);
        float c[4][4];
#pragma unroll
        for (int j = 0; j < 4; ++j)
#pragma unroll
            for (int k = 0; k < 4; ++k) c[j][k] = 0.f;
        mma_tile(Ap, Wp, wm, wn, lane, c);
        __syncthreads();
        int r0 = tile * TILE_M + wm + g;
#pragma unroll
        for (int nf = 0; nf < 4; ++nf) {
            int col = wn + nf * 8 + t * 2;
            if (r0 < M)
                *(float2*)&out[(size_t)r0 * DIM + col] =
                    make_float2(c[nf][0] + bias2[nf].x,
                                c[nf][1] + bias2[nf].y);
            if (r0 + 8 < M)
                *(float2*)&out[(size_t)(r0 + 8) * DIM + col] =
                    make_float2(c[nf][2] + bias2[nf].x,
                                c[nf][3] + bias2[nf].y);
        }
    }
}

// ---------------------------------------------------------------------------
// Fused edge kernel: proj = e @ We + be, then score/e_out/s/scatter
// ---------------------------------------------------------------------------
__global__ __launch_bounds__(THREADS, 2)
void gemm_edge(const float* __restrict__ Ein, const float* __restrict__ W,
               const float* __restrict__ bias, const int* __restrict__ src,
               const int* __restrict__ dst, float* __restrict__ hacc,
               float* __restrict__ eout) {
    extern __shared__ uint2 smem[];
    uint2* Wp = smem;
    uint2* Ap = smem + SMEM_W_U2;
    float* Cs = (float*)Ap;  // union: C staging reuses A region
    int tid = threadIdx.x, lane = tid & 31, warp = tid >> 5;
    int wm = (warp & 3) * 16, wn = (warp >> 2) * 32;
    int g = lane >> 2, t = lane & 3;

    stage_W(Wp, W);
    float4 be4 = *(const float4*)&bias[lane * 4];

    const int nTiles = N_EDGES / TILE_M;  // 12500 exact
    int tile = blockIdx.x;
    float4 cur[4];
    if (tile < nTiles) prefetch_A<true>(cur, Ein, tile * TILE_M, N_EDGES, tid);
    __syncthreads();

#pragma unroll 1
    for (; tile < nTiles; tile += gridDim.x) {
        store_A(Ap, cur, tid);
        __syncthreads();
        float c[4][4];
#pragma unroll
        for (int j = 0; j < 4; ++j)
#pragma unroll
            for (int k = 0; k < 4; ++k) c[j][k] = 0.f;
        mma_tile(Ap, Wp, wm, wn, lane, c);
        // prefetch next tile: overlaps Cs-write + gather/scatter epilogue
        int nxt = tile + gridDim.x;
        if (nxt < nTiles) prefetch_A<true>(cur, Ein, nxt * TILE_M, N_EDGES, tid);
        __syncthreads();  // Ap reads done -> safe to overwrite with Cs
        {
            int rr = wm + g;
#pragma unroll
            for (int nf = 0; nf < 4; ++nf) {
                int col = wn + nf * 8 + t * 2;
                *(float2*)&Cs[rr * CS_STRIDE + col] =
                    make_float2(c[nf][0], c[nf][1]);
                *(float2*)&Cs[(rr + 8) * CS_STRIDE + col] =
                    make_float2(c[nf][2], c[nf][3]);
            }
        }
        __syncthreads();

        // epilogue: each warp owns 4 edges of this tile
        int rbase = warp * 4;
        int ebase = tile * TILE_M + rbase;
        int sn[4], dn[4];
#pragma unroll
        for (int i = 0; i < 4; ++i) {
            sn[i] = __ldg(&src[ebase + i]);
            dn[i] = __ldg(&dst[ebase + i]);
        }
#pragma unroll 2
        for (int i = 0; i < 4; ++i) {
            float4 q = *(const float4*)&g_Q[(size_t)dn[i] * DIM + lane * 4];
            float4 kk = *(const float4*)&g_K[(size_t)sn[i] * DIM + lane * 4];
            float4 vv = *(const float4*)&g_V[(size_t)sn[i] * DIM + lane * 4];
            float4 pr = *(float4*)&Cs[(rbase + i) * CS_STRIDE + lane * 4];
            pr.x += be4.x; pr.y += be4.y; pr.z += be4.z; pr.w += be4.w;
            float4 sc;
            sc.x = q.x * kk.x * 0.25f * pr.x;
            sc.y = q.y * kk.y * 0.25f * pr.y;
            sc.z = q.z * kk.z * 0.25f * pr.z;
            sc.w = q.w * kk.w * 0.25f * pr.w;
            __stcs((float4*)&eout[(size_t)(ebase + i) * DIM + lane * 4], sc);
            float hs = sc.x + sc.y + sc.z + sc.w;
            hs += __shfl_xor_sync(0xffffffffu, hs, 1);
            hs += __shfl_xor_sync(0xffffffffu, hs, 2);
            float s = expf(fminf(fmaxf(hs, -5.f), 5.f));
            float4 add = make_float4(vv.x * s, vv.y * s, vv.z * s, vv.w * s);
            red_add_v4(&hacc[(size_t)dn[i] * DIM + lane * 4], add);
            if ((lane & 3) == 0)
                red_add_f32(&g_z[dn[i] * HEADS + (lane >> 2)], s);
        }
        __syncthreads();  // Cs reads done before next tile's stage_A
    }
}

// ---------------------------------------------------------------------------
// finalize: h_out = wV / (z + 1e-6)
// ---------------------------------------------------------------------------
__global__ void finalize_kernel(float* __restrict__ hacc) {
    int i = blockIdx.x * blockDim.x + threadIdx.x;
    if (i < N_NODES * DIM) {
        int node = i >> 7;
        int head = (i >> 4) & 7;
        hacc[i] = hacc[i] / (g_z[node * HEADS + head] + 1e-6f);
    }
}

// ---------------------------------------------------------------------------
// launch
// ---------------------------------------------------------------------------
extern "C" void kernel_launch(void* const* d_in, const int* in_sizes, int n_in,
                              void* d_out, int out_size) {
    const float* h  = (const float*)d_in[0];
    const float* e  = (const float*)d_in[1];
    const int*   src = (const int*)d_in[2];
    const int*   dst = (const int*)d_in[3];
    const float* Wq = (const float*)d_in[4];
    const float* bq = (const float*)d_in[5];
    const float* Wk = (const float*)d_in[6];
    const float* bk = (const float*)d_in[7];
    const float* Wv = (const float*)d_in[8];
    const float* bv = (const float*)d_in[9];
    const float* We = (const float*)d_in[10];
    const float* be = (const float*)d_in[11];

    float* out  = (float*)d_out;
    float* hacc = out;                               // [N,H,D] accumulator -> h_out
    float* eout = out + (size_t)N_NODES * DIM;       // [E,H,D] e_out

    float *qp, *kp, *vp, *zp;
    cudaGetSymbolAddress((void**)&qp, g_Q);
    cudaGetSymbolAddress((void**)&kp, g_K);
    cudaGetSymbolAddress((void**)&vp, g_V);
    cudaGetSymbolAddress((void**)&zp, g_z);

    cudaFuncSetAttribute(gemm_node, cudaFuncAttributeMaxDynamicSharedMemorySize, SMEM_BYTES);
    cudaFuncSetAttribute(gemm_edge, cudaFuncAttributeMaxDynamicSharedMemorySize, SMEM_BYTES);

    cudaMemsetAsync(hacc, 0, (size_t)N_NODES * DIM * sizeof(float));
    cudaMemsetAsync(zp, 0, (size_t)N_NODES * HEADS * sizeof(float));

    dim3 ngrid(GRID, 3);
    gemm_node<<<ngrid, THREADS, SMEM_BYTES>>>(h, Wq, Wk, Wv, bq, bk, bv,
                                              qp, kp, vp, N_NODES);
    gemm_edge<<<GRID, THREADS, SMEM_BYTES>>>(e, We, be, src, dst, hacc, eout);
    finalize_kernel<<<(N_NODES * DIM + 255) / 256, 256>>>(hacc);
}